// round 2
// baseline (speedup 1.0000x reference)
#include <cuda_runtime.h>
#include <cstdint>
#include <math.h>

#define B_SZ   8192
#define E_SZ   4096
#define DEMB   256
#define HID    1024
#define DIS    128
#define SYM    512
#define DSYM   (DIS + SYM)   // 640

// ---------------- scratch (device globals; no allocation allowed) ----------
__device__ float g_graph_rep[E_SZ * DEMB];   // relu(kg_adj @ W_g)
__device__ float g_state    [B_SZ * DEMB];   // dialog_sym_rep @ graph_rep
__device__ float g_state_   [B_SZ * DSYM];   // ternary state
__device__ float g_symmaskf [B_SZ * SYM];    // sym_mask as f32
__device__ float g_dlogits  [B_SZ * DIS];    // pre-softmax disease logits
__device__ float g_h_mu     [B_SZ * HID];    // relu(state_ @ Wm1 + bm1)
__device__ float g_mu       [B_SZ];          // sigmoid(h_mu @ Wm2 + bm2)
__device__ float g_h1       [B_SZ * HID];    // relu(state @ W1 + b1)
__device__ float g_symp     [B_SZ * SYM];    // sigmoid(h1 @ W2 + b2)

// ---------------- helpers ---------------------------------------------------
__device__ __forceinline__ uint32_t f2tf32(float x) {
    uint32_t r;
    asm("cvt.rna.tf32.f32 %0, %1;" : "=r"(r) : "f"(x));
    return r;
}

__device__ __forceinline__ float sigm(float x) { return 1.0f / (1.0f + expf(-x)); }

__device__ __forceinline__ void mma_tf32(float& c0, float& c1, float& c2, float& c3,
                                         uint32_t a0, uint32_t a1, uint32_t a2, uint32_t a3,
                                         uint32_t b0, uint32_t b1) {
    asm volatile(
        "mma.sync.aligned.m16n8k8.row.col.f32.tf32.tf32.f32 "
        "{%0,%1,%2,%3}, {%4,%5,%6,%7}, {%8,%9}, {%0,%1,%2,%3};"
        : "+f"(c0), "+f"(c1), "+f"(c2), "+f"(c3)
        : "r"(a0), "r"(a1), "r"(a2), "r"(a3), "r"(b0), "r"(b1));
}

// ---------------- generic tf32 GEMM: C = act(A[MxK] @ B[KxN] + bias) --------
// EPI: 0 = none, 1 = relu, 2 = sigmoid, 3 = combine (final symptom output)
// Requirements (all satisfied here): M%128==0, N%128==0, K%32==0.
template <int EPI>
__global__ void __launch_bounds__(256, 2)
gemm_tf32(const float* __restrict__ A, const float* __restrict__ Bm,
          float* __restrict__ C, const float* __restrict__ bias,
          int M, int N, int K,
          const float* __restrict__ mu,    // EPI3
          const float* __restrict__ symp,  // EPI3
          const int*   __restrict__ flag1, // EPI3 sym_flag
          const int*   __restrict__ flag2) // EPI3 symptoms_mask
{
    __shared__ uint32_t As[128][33];   // [m][k] tf32
    __shared__ uint32_t Bs[32][129];   // [k][n] tf32

    const int tid    = threadIdx.x;
    const int lane   = tid & 31;
    const int warpId = tid >> 5;       // 0..7
    const int warpM  = warpId >> 2;    // 0..1  (64 rows each)
    const int warpN  = warpId & 3;     // 0..3  (32 cols each)

    const int bm0 = blockIdx.y * 128;
    const int bn0 = blockIdx.x * 128;

    float acc[4][4][4];
    #pragma unroll
    for (int mi = 0; mi < 4; mi++)
        #pragma unroll
        for (int ni = 0; ni < 4; ni++)
            #pragma unroll
            for (int j = 0; j < 4; j++) acc[mi][ni][j] = 0.0f;

    const int nkt = K >> 5;
    for (int kt = 0; kt < nkt; kt++) {
        // ---- load A tile (128 x 32) ----
        {
            const float* Ap = A + (long)bm0 * K + (kt << 5);
            #pragma unroll
            for (int i = 0; i < 4; i++) {
                int id = tid + (i << 8);          // 0..1023
                int r  = id >> 3;                 // /8
                int c4 = (id & 7) << 2;           // *4
                float4 v = *reinterpret_cast<const float4*>(Ap + (long)r * K + c4);
                As[r][c4 + 0] = f2tf32(v.x);
                As[r][c4 + 1] = f2tf32(v.y);
                As[r][c4 + 2] = f2tf32(v.z);
                As[r][c4 + 3] = f2tf32(v.w);
            }
        }
        // ---- load B tile (32 x 128) ----
        {
            const float* Bp = Bm + (long)(kt << 5) * N + bn0;
            #pragma unroll
            for (int i = 0; i < 4; i++) {
                int id = tid + (i << 8);
                int r  = id >> 5;                 // /32
                int c4 = (id & 31) << 2;
                float4 v = *reinterpret_cast<const float4*>(Bp + (long)r * N + c4);
                Bs[r][c4 + 0] = f2tf32(v.x);
                Bs[r][c4 + 1] = f2tf32(v.y);
                Bs[r][c4 + 2] = f2tf32(v.z);
                Bs[r][c4 + 3] = f2tf32(v.w);
            }
        }
        __syncthreads();

        const int g = lane >> 2;       // 0..7
        const int t = lane & 3;        // 0..3
        #pragma unroll
        for (int ks = 0; ks < 4; ks++) {
            const int k0 = ks << 3;
            uint32_t a[4][4], b[4][2];
            #pragma unroll
            for (int mi = 0; mi < 4; mi++) {
                int r = (warpM << 6) + (mi << 4) + g;
                a[mi][0] = As[r    ][k0 + t];
                a[mi][1] = As[r + 8][k0 + t];
                a[mi][2] = As[r    ][k0 + t + 4];
                a[mi][3] = As[r + 8][k0 + t + 4];
            }
            #pragma unroll
            for (int ni = 0; ni < 4; ni++) {
                int c = (warpN << 5) + (ni << 3) + g;
                b[ni][0] = Bs[k0 + t    ][c];
                b[ni][1] = Bs[k0 + t + 4][c];
            }
            #pragma unroll
            for (int mi = 0; mi < 4; mi++)
                #pragma unroll
                for (int ni = 0; ni < 4; ni++)
                    mma_tf32(acc[mi][ni][0], acc[mi][ni][1], acc[mi][ni][2], acc[mi][ni][3],
                             a[mi][0], a[mi][1], a[mi][2], a[mi][3],
                             b[ni][0], b[ni][1]);
        }
        __syncthreads();
    }

    // ---- epilogue ----
    const int g = lane >> 2;
    const int t = lane & 3;
    #pragma unroll
    for (int mi = 0; mi < 4; mi++) {
        #pragma unroll
        for (int ni = 0; ni < 4; ni++) {
            int row0 = bm0 + (warpM << 6) + (mi << 4) + g;
            int col  = bn0 + (warpN << 5) + (ni << 3) + (t << 1);
            #pragma unroll
            for (int half = 0; half < 2; half++) {   // half 0: rows row0, half 1: row0+8
                int row = row0 + (half << 3);
                float v0 = acc[mi][ni][half * 2 + 0];
                float v1 = acc[mi][ni][half * 2 + 1];
                if (bias) { v0 += bias[col]; v1 += bias[col + 1]; }
                if (EPI == 1) { v0 = fmaxf(v0, 0.0f); v1 = fmaxf(v1, 0.0f); }
                if (EPI == 2) { v0 = sigm(v0); v1 = sigm(v1); }
                long o = (long)row * N + col;
                if (EPI == 3) {
                    // v = sym_tfidf; filter_sig then blend with mu & symptom_p, apply flags
                    float m  = mu[row];
                    float tf0 = v0 > 0.0f ? sigm(v0) : v0;
                    float tf1 = v1 > 0.0f ? sigm(v1) : v1;
                    float p0 = symp[o], p1 = symp[o + 1];
                    float f0 = (float)(flag1[o]     * flag2[o]);
                    float f1 = (float)(flag1[o + 1] * flag2[o + 1]);
                    C[o]     = (m * p0 + (1.0f - m) * tf0) * f0;
                    C[o + 1] = (m * p1 + (1.0f - m) * tf1) * f1;
                } else {
                    C[o]     = v0;
                    C[o + 1] = v1;
                }
            }
        }
    }
}

// ---------------- small kernels --------------------------------------------
__global__ void conv_state_kernel(const int* __restrict__ ds, float* __restrict__ st, int n) {
    int i = blockIdx.x * blockDim.x + threadIdx.x;
    if (i < n) {
        int v = ds[i];
        st[i] = (v == 1) ? 1.0f : ((v == -1) ? -1.0f : 0.0f);
    }
}

__global__ void conv_f32_kernel(const int* __restrict__ m, float* __restrict__ f, int n) {
    int i = blockIdx.x * blockDim.x + threadIdx.x;
    if (i < n) f[i] = (float)m[i];
}

// softmax over DIS=128 per row, then * disease_mask -> out_dis. One warp/row.
__global__ void softmax_mask_kernel(const float* __restrict__ logits,
                                    const int* __restrict__ dmask,
                                    float* __restrict__ outd) {
    int warp = (blockIdx.x * blockDim.x + threadIdx.x) >> 5;
    int lane = threadIdx.x & 31;
    if (warp >= B_SZ) return;
    const float4 v = reinterpret_cast<const float4*>(logits + (long)warp * DIS)[lane];
    float mx = fmaxf(fmaxf(v.x, v.y), fmaxf(v.z, v.w));
    #pragma unroll
    for (int o = 16; o; o >>= 1) mx = fmaxf(mx, __shfl_xor_sync(0xFFFFFFFFu, mx, o));
    float e0 = expf(v.x - mx), e1 = expf(v.y - mx), e2 = expf(v.z - mx), e3 = expf(v.w - mx);
    float s = e0 + e1 + e2 + e3;
    #pragma unroll
    for (int o = 16; o; o >>= 1) s += __shfl_xor_sync(0xFFFFFFFFu, s, o);
    float inv = 1.0f / s;
    const int4 m4 = reinterpret_cast<const int4*>(dmask + (long)warp * DIS)[lane];
    float4 o4;
    o4.x = e0 * inv * (float)m4.x;
    o4.y = e1 * inv * (float)m4.y;
    o4.z = e2 * inv * (float)m4.z;
    o4.w = e3 * inv * (float)m4.w;
    reinterpret_cast<float4*>(outd + (long)warp * DIS)[lane] = o4;
}

// mu = sigmoid(h[B,HID] @ Wm2[HID] + bm2). One warp per row.
__global__ void mu_kernel(const float* __restrict__ h, const float* __restrict__ Wm2,
                          const float* __restrict__ bm2, float* __restrict__ mu) {
    int warp = (blockIdx.x * blockDim.x + threadIdx.x) >> 5;
    int lane = threadIdx.x & 31;
    if (warp >= B_SZ) return;
    const float4* hp = reinterpret_cast<const float4*>(h + (long)warp * HID);
    const float4* wp = reinterpret_cast<const float4*>(Wm2);
    float s = 0.0f;
    #pragma unroll
    for (int i = lane; i < HID / 4; i += 32) {
        float4 a = hp[i], b = wp[i];
        s += a.x * b.x + a.y * b.y + a.z * b.z + a.w * b.w;
    }
    #pragma unroll
    for (int o = 16; o; o >>= 1) s += __shfl_xor_sync(0xFFFFFFFFu, s, o);
    if (lane == 0) mu[warp] = sigm(s + bm2[0]);
}

// ---------------- launch -----------------------------------------------------
extern "C" void kernel_launch(void* const* d_in, const int* in_sizes, int n_in,
                              void* d_out, int out_size) {
    const int*   dialog_state   = (const int*)  d_in[0];
    const float* dialog_sym_rep = (const float*)d_in[1];
    const float* kg_adj         = (const float*)d_in[2];
    const int*   sym_flag       = (const int*)  d_in[3];
    const int*   sym_mask       = (const int*)  d_in[4];
    const int*   disease_mask   = (const int*)  d_in[5];
    const int*   symptoms_mask  = (const int*)  d_in[6];
    const float* W_g  = (const float*)d_in[7];
    const float* Wd1  = (const float*)d_in[8];
    const float* bd1  = (const float*)d_in[9];
    const float* W1   = (const float*)d_in[10];
    const float* b1   = (const float*)d_in[11];
    const float* W2   = (const float*)d_in[12];
    const float* b2   = (const float*)d_in[13];
    const float* Wm1  = (const float*)d_in[14];
    const float* bm1  = (const float*)d_in[15];
    const float* Wm2  = (const float*)d_in[16];
    const float* bm2  = (const float*)d_in[17];
    const float* m_d  = (const float*)d_in[18];

    float* out_dis = (float*)d_out;                      // [B, DIS]
    float* out_sym = out_dis + (long)B_SZ * DIS;         // [B, SYM]

    float *graph_p, *state_p, *stateT_p, *symmask_p, *dlog_p, *hmu_p, *mu_p, *h1_p, *symp_p;
    cudaGetSymbolAddress((void**)&graph_p,   g_graph_rep);
    cudaGetSymbolAddress((void**)&state_p,   g_state);
    cudaGetSymbolAddress((void**)&stateT_p,  g_state_);
    cudaGetSymbolAddress((void**)&symmask_p, g_symmaskf);
    cudaGetSymbolAddress((void**)&dlog_p,    g_dlogits);
    cudaGetSymbolAddress((void**)&hmu_p,     g_h_mu);
    cudaGetSymbolAddress((void**)&mu_p,      g_mu);
    cudaGetSymbolAddress((void**)&h1_p,      g_h1);
    cudaGetSymbolAddress((void**)&symp_p,    g_symp);

    const int TB = 256;

    // mask conversions
    {
        int n1 = B_SZ * DSYM;
        conv_state_kernel<<<(n1 + TB - 1) / TB, TB>>>(dialog_state, stateT_p, n1);
        int n2 = B_SZ * SYM;
        conv_f32_kernel<<<(n2 + TB - 1) / TB, TB>>>(sym_mask, symmask_p, n2);
    }

    // graph_rep = relu(kg_adj @ W_g)            [4096 x 256], K=4096
    gemm_tf32<1><<<dim3(DEMB / 128, E_SZ / 128), TB>>>(
        kg_adj, W_g, graph_p, nullptr, E_SZ, DEMB, E_SZ,
        nullptr, nullptr, nullptr, nullptr);

    // state = dialog_sym_rep @ graph_rep        [8192 x 256], K=4096
    gemm_tf32<0><<<dim3(DEMB / 128, B_SZ / 128), TB>>>(
        dialog_sym_rep, graph_p, state_p, nullptr, B_SZ, DEMB, E_SZ,
        nullptr, nullptr, nullptr, nullptr);

    // disease logits = symmask @ Wd1 + bd1      [8192 x 128], K=512
    gemm_tf32<0><<<dim3(DIS / 128, B_SZ / 128), TB>>>(
        symmask_p, Wd1, dlog_p, bd1, B_SZ, DIS, SYM,
        nullptr, nullptr, nullptr, nullptr);

    // disease_dis = softmax(logits) * disease_mask -> out_dis
    softmax_mask_kernel<<<(B_SZ * 32 + TB - 1) / TB, TB>>>(dlog_p, disease_mask, out_dis);

    // h_mu = relu(state_ @ Wm1 + bm1)           [8192 x 1024], K=640
    gemm_tf32<1><<<dim3(HID / 128, B_SZ / 128), TB>>>(
        stateT_p, Wm1, hmu_p, bm1, B_SZ, HID, DSYM,
        nullptr, nullptr, nullptr, nullptr);

    // mu = sigmoid(h_mu @ Wm2 + bm2)            [8192 x 1]
    mu_kernel<<<(B_SZ * 32 + TB - 1) / TB, TB>>>(hmu_p, Wm2, bm2, mu_p);

    // h1 = relu(state @ W1 + b1)                [8192 x 1024], K=256
    gemm_tf32<1><<<dim3(HID / 128, B_SZ / 128), TB>>>(
        state_p, W1, h1_p, b1, B_SZ, HID, DEMB,
        nullptr, nullptr, nullptr, nullptr);

    // symptom_p = sigmoid(h1 @ W2 + b2)         [8192 x 512], K=1024
    gemm_tf32<2><<<dim3(SYM / 128, B_SZ / 128), TB>>>(
        h1_p, W2, symp_p, b2, B_SZ, SYM, HID,
        nullptr, nullptr, nullptr, nullptr);

    // final: sym_tfidf = disease_dis @ m_d; combine epilogue -> out_sym
    gemm_tf32<3><<<dim3(SYM / 128, B_SZ / 128), TB>>>(
        out_dis, m_d, out_sym, nullptr, B_SZ, SYM, DIS,
        mu_p, symp_p, sym_flag, symptoms_mask);
}

// round 3
// speedup vs baseline: 1.8940x; 1.8940x over previous
#include <cuda_runtime.h>
#include <cstdint>
#include <math.h>

#define B_SZ   8192
#define E_SZ   4096
#define DEMB   256
#define HID    1024
#define DIS    128
#define SYM    512
#define DSYM   (DIS + SYM)   // 640

// ---------------- scratch (device globals; no allocation allowed) ----------
__device__ float g_graph_rep[E_SZ * DEMB];   // relu(kg_adj @ W_g)
__device__ float g_state    [B_SZ * DEMB];   // dialog_sym_rep @ graph_rep
__device__ float g_dlogits  [B_SZ * DIS];    // pre-softmax disease logits
__device__ float g_h_mu     [B_SZ * HID];    // relu(state_ @ Wm1 + bm1)
__device__ float g_mu       [B_SZ];          // sigmoid(h_mu @ Wm2 + bm2)
__device__ float g_h1       [B_SZ * HID];    // relu(state @ W1 + b1)
__device__ float g_symp     [B_SZ * SYM];    // sigmoid(h1 @ W2 + b2)

// ---------------- helpers ---------------------------------------------------
__device__ __forceinline__ uint32_t f2tf32(float x) {
    uint32_t r;
    asm("cvt.rna.tf32.f32 %0, %1;" : "=r"(r) : "f"(x));
    return r;
}

__device__ __forceinline__ float sigm(float x) { return 1.0f / (1.0f + expf(-x)); }

__device__ __forceinline__ void mma_tf32(float& c0, float& c1, float& c2, float& c3,
                                         uint32_t a0, uint32_t a1, uint32_t a2, uint32_t a3,
                                         uint32_t b0, uint32_t b1) {
    asm volatile(
        "mma.sync.aligned.m16n8k8.row.col.f32.tf32.tf32.f32 "
        "{%0,%1,%2,%3}, {%4,%5,%6,%7}, {%8,%9}, {%0,%1,%2,%3};"
        : "+f"(c0), "+f"(c1), "+f"(c2), "+f"(c3)
        : "r"(a0), "r"(a1), "r"(a2), "r"(a3), "r"(b0), "r"(b1));
}

// ---------------- tf32 GEMM: C = act(A[MxK] @ B[KxN] + bias) ----------------
// EPI:   0 none, 1 relu, 2 sigmoid, 3 final-combine
// BM:    128 (warp 64x32, MI=4) or 64 (warp 32x32, MI=2). BN fixed 128.
// ACONV: 0 A=float, 1 A=int ternary(+1/-1 keep, else 0), 2 A=int cast
//
// SMEM layout uses k-permutation q(k) = (k&3)*8 + (k>>2), pitch 36 words.
// Thread (g=lane>>2, t=lane&3) reads its 8 per-row k-values (k&3==t) as two
// contiguous float4s -> all fragment loads are conflict-free LDS.128.
template <int EPI, int BM, int ACONV>
__global__ void __launch_bounds__(256, 2)
gemm_tf32(const void* __restrict__ Av, const float* __restrict__ Bmat,
          float* __restrict__ C, const float* __restrict__ bias,
          int M, int N, int K,
          const float* __restrict__ mu,    // EPI3
          const float* __restrict__ symp,  // EPI3
          const int*   __restrict__ flag1, // EPI3 sym_flag
          const int*   __restrict__ flag2) // EPI3 symptoms_mask
{
    constexpr int MI    = BM / 32;   // mma row-tiles per warp
    constexpr int WROWS = BM / 2;    // rows per warpM slice

    __shared__ uint32_t As[BM][36];
    __shared__ uint32_t Bs[128][36];

    const int tid    = threadIdx.x;
    const int lane   = tid & 31;
    const int warpId = tid >> 5;       // 0..7
    const int warpM  = warpId >> 2;    // 0..1
    const int warpN  = warpId & 3;     // 0..3
    const int g      = lane >> 2;      // 0..7
    const int t      = lane & 3;       // 0..3

    const int bm0 = blockIdx.y * BM;
    const int bn0 = blockIdx.x * 128;

    float acc[MI][4][4];
    #pragma unroll
    for (int mi = 0; mi < MI; mi++)
        #pragma unroll
        for (int ni = 0; ni < 4; ni++)
            #pragma unroll
            for (int j = 0; j < 4; j++) acc[mi][ni][j] = 0.0f;

    const int nkt = K >> 5;
    for (int kt = 0; kt < nkt; kt++) {
        const int k0g = kt << 5;

        // ---- A fill: each thread loads 4 consecutive k (float4/int4), scatters
        //      to q = j*8 + (k>>2). STS pattern is 8 consecutive words/quarter. --
        #pragma unroll
        for (int i = 0; i < MI; i++) {
            int id = tid + (i << 8);           // < BM*8
            int r  = id >> 3;
            int kq = (id & 7) << 2;
            float x, y, z, w;
            if (ACONV == 0) {
                const float* ap = (const float*)Av + (long)(bm0 + r) * K + k0g + kq;
                float4 v = *reinterpret_cast<const float4*>(ap);
                x = v.x; y = v.y; z = v.z; w = v.w;
            } else {
                const int* ap = (const int*)Av + (long)(bm0 + r) * K + k0g + kq;
                int4 v = *reinterpret_cast<const int4*>(ap);
                if (ACONV == 1) {
                    x = (v.x == 1) ? 1.0f : ((v.x == -1) ? -1.0f : 0.0f);
                    y = (v.y == 1) ? 1.0f : ((v.y == -1) ? -1.0f : 0.0f);
                    z = (v.z == 1) ? 1.0f : ((v.z == -1) ? -1.0f : 0.0f);
                    w = (v.w == 1) ? 1.0f : ((v.w == -1) ? -1.0f : 0.0f);
                } else {
                    x = (float)v.x; y = (float)v.y; z = (float)v.z; w = (float)v.w;
                }
            }
            int q = id & 7;                    // (k>>2) within tile
            As[r][q + 0 ] = f2tf32(x);
            As[r][q + 8 ] = f2tf32(y);
            As[r][q + 16] = f2tf32(z);
            As[r][q + 24] = f2tf32(w);
        }

        // ---- B fill (transposed+permuted): thread loads 4 k's with same k&3
        //      (coalesced 32b across c), stores one STS.128 at Bs[c][t*8+h*4]. --
        #pragma unroll
        for (int i = 0; i < 4; i++) {
            int id = tid + (i << 8);           // < 1024
            int c  = id & 127;
            int tt = (id >> 7) & 3;
            int hh = (id >> 9) & 1;
            const float* bp = Bmat + (long)(k0g + (hh << 4) + tt) * N + bn0 + c;
            uint4 s;
            s.x = f2tf32(bp[0]);
            s.y = f2tf32(bp[(long)4  * N]);
            s.z = f2tf32(bp[(long)8  * N]);
            s.w = f2tf32(bp[(long)12 * N]);
            *reinterpret_cast<uint4*>(&Bs[c][(tt << 3) + (hh << 2)]) = s;
        }
        __syncthreads();

        // ---- compute: 2 halves, each covering ks = 2h, 2h+1 ----
        #pragma unroll
        for (int h = 0; h < 2; h++) {
            const int qo = (t << 3) + (h << 2);
            uint4 al[MI], ah[MI], bb[4];
            #pragma unroll
            for (int mi = 0; mi < MI; mi++) {
                int r0 = warpM * WROWS + (mi << 4) + g;
                al[mi] = *reinterpret_cast<const uint4*>(&As[r0    ][qo]);
                ah[mi] = *reinterpret_cast<const uint4*>(&As[r0 + 8][qo]);
            }
            #pragma unroll
            for (int ni = 0; ni < 4; ni++) {
                int c = (warpN << 5) + (ni << 3) + g;
                bb[ni] = *reinterpret_cast<const uint4*>(&Bs[c][qo]);
            }
            #pragma unroll
            for (int mi = 0; mi < MI; mi++)
                #pragma unroll
                for (int ni = 0; ni < 4; ni++) {
                    // ks = 2h
                    mma_tf32(acc[mi][ni][0], acc[mi][ni][1], acc[mi][ni][2], acc[mi][ni][3],
                             al[mi].x, ah[mi].x, al[mi].y, ah[mi].y, bb[ni].x, bb[ni].y);
                    // ks = 2h+1
                    mma_tf32(acc[mi][ni][0], acc[mi][ni][1], acc[mi][ni][2], acc[mi][ni][3],
                             al[mi].z, ah[mi].z, al[mi].w, ah[mi].w, bb[ni].z, bb[ni].w);
                }
        }
        __syncthreads();
    }

    // ---- epilogue ----
    #pragma unroll
    for (int mi = 0; mi < MI; mi++) {
        #pragma unroll
        for (int ni = 0; ni < 4; ni++) {
            int row0 = bm0 + warpM * WROWS + (mi << 4) + g;
            int col  = bn0 + (warpN << 5) + (ni << 3) + (t << 1);
            #pragma unroll
            for (int half = 0; half < 2; half++) {
                int row = row0 + (half << 3);
                float v0 = acc[mi][ni][half * 2 + 0];
                float v1 = acc[mi][ni][half * 2 + 1];
                if (bias) { v0 += bias[col]; v1 += bias[col + 1]; }
                if (EPI == 1) { v0 = fmaxf(v0, 0.0f); v1 = fmaxf(v1, 0.0f); }
                if (EPI == 2) { v0 = sigm(v0); v1 = sigm(v1); }
                long o = (long)row * N + col;
                if (EPI == 3) {
                    float m   = mu[row];
                    float tf0 = v0 > 0.0f ? sigm(v0) : v0;
                    float tf1 = v1 > 0.0f ? sigm(v1) : v1;
                    float p0  = symp[o], p1 = symp[o + 1];
                    float f0  = (float)(flag1[o]     * flag2[o]);
                    float f1  = (float)(flag1[o + 1] * flag2[o + 1]);
                    C[o]     = (m * p0 + (1.0f - m) * tf0) * f0;
                    C[o + 1] = (m * p1 + (1.0f - m) * tf1) * f1;
                } else {
                    C[o]     = v0;
                    C[o + 1] = v1;
                }
            }
        }
    }
}

// ---------------- small kernels ---------------------------------------------
// softmax over DIS=128 per row, then * disease_mask -> out_dis. One warp/row.
__global__ void softmax_mask_kernel(const float* __restrict__ logits,
                                    const int* __restrict__ dmask,
                                    float* __restrict__ outd) {
    int warp = (blockIdx.x * blockDim.x + threadIdx.x) >> 5;
    int lane = threadIdx.x & 31;
    if (warp >= B_SZ) return;
    const float4 v = reinterpret_cast<const float4*>(logits + (long)warp * DIS)[lane];
    float mx = fmaxf(fmaxf(v.x, v.y), fmaxf(v.z, v.w));
    #pragma unroll
    for (int o = 16; o; o >>= 1) mx = fmaxf(mx, __shfl_xor_sync(0xFFFFFFFFu, mx, o));
    float e0 = expf(v.x - mx), e1 = expf(v.y - mx), e2 = expf(v.z - mx), e3 = expf(v.w - mx);
    float s = e0 + e1 + e2 + e3;
    #pragma unroll
    for (int o = 16; o; o >>= 1) s += __shfl_xor_sync(0xFFFFFFFFu, s, o);
    float inv = 1.0f / s;
    const int4 m4 = reinterpret_cast<const int4*>(dmask + (long)warp * DIS)[lane];
    float4 o4;
    o4.x = e0 * inv * (float)m4.x;
    o4.y = e1 * inv * (float)m4.y;
    o4.z = e2 * inv * (float)m4.z;
    o4.w = e3 * inv * (float)m4.w;
    reinterpret_cast<float4*>(outd + (long)warp * DIS)[lane] = o4;
}

// mu = sigmoid(h[B,HID] @ Wm2[HID] + bm2). One warp per row.
__global__ void mu_kernel(const float* __restrict__ h, const float* __restrict__ Wm2,
                          const float* __restrict__ bm2, float* __restrict__ mu) {
    int warp = (blockIdx.x * blockDim.x + threadIdx.x) >> 5;
    int lane = threadIdx.x & 31;
    if (warp >= B_SZ) return;
    const float4* hp = reinterpret_cast<const float4*>(h + (long)warp * HID);
    const float4* wp = reinterpret_cast<const float4*>(Wm2);
    float s = 0.0f;
    #pragma unroll
    for (int i = lane; i < HID / 4; i += 32) {
        float4 a = hp[i], b = wp[i];
        s += a.x * b.x + a.y * b.y + a.z * b.z + a.w * b.w;
    }
    #pragma unroll
    for (int o = 16; o; o >>= 1) s += __shfl_xor_sync(0xFFFFFFFFu, s, o);
    if (lane == 0) mu[warp] = sigm(s + bm2[0]);
}

// ---------------- launch -----------------------------------------------------
extern "C" void kernel_launch(void* const* d_in, const int* in_sizes, int n_in,
                              void* d_out, int out_size) {
    const int*   dialog_state   = (const int*)  d_in[0];
    const float* dialog_sym_rep = (const float*)d_in[1];
    const float* kg_adj         = (const float*)d_in[2];
    const int*   sym_flag       = (const int*)  d_in[3];
    const int*   sym_mask       = (const int*)  d_in[4];
    const int*   disease_mask   = (const int*)  d_in[5];
    const int*   symptoms_mask  = (const int*)  d_in[6];
    const float* W_g  = (const float*)d_in[7];
    const float* Wd1  = (const float*)d_in[8];
    const float* bd1  = (const float*)d_in[9];
    const float* W1   = (const float*)d_in[10];
    const float* b1   = (const float*)d_in[11];
    const float* W2   = (const float*)d_in[12];
    const float* b2   = (const float*)d_in[13];
    const float* Wm1  = (const float*)d_in[14];
    const float* bm1  = (const float*)d_in[15];
    const float* Wm2  = (const float*)d_in[16];
    const float* bm2  = (const float*)d_in[17];
    const float* m_d  = (const float*)d_in[18];

    float* out_dis = (float*)d_out;                      // [B, DIS]
    float* out_sym = out_dis + (long)B_SZ * DIS;         // [B, SYM]

    float *graph_p, *state_p, *dlog_p, *hmu_p, *mu_p, *h1_p, *symp_p;
    cudaGetSymbolAddress((void**)&graph_p, g_graph_rep);
    cudaGetSymbolAddress((void**)&state_p, g_state);
    cudaGetSymbolAddress((void**)&dlog_p,  g_dlogits);
    cudaGetSymbolAddress((void**)&hmu_p,   g_h_mu);
    cudaGetSymbolAddress((void**)&mu_p,    g_mu);
    cudaGetSymbolAddress((void**)&h1_p,    g_h1);
    cudaGetSymbolAddress((void**)&symp_p,  g_symp);

    const int TB = 256;

    // graph_rep = relu(kg_adj @ W_g)        [4096 x 256], K=4096  (BM=64 -> 128 blocks)
    gemm_tf32<1, 64, 0><<<dim3(DEMB / 128, E_SZ / 64), TB>>>(
        kg_adj, W_g, graph_p, nullptr, E_SZ, DEMB, E_SZ,
        nullptr, nullptr, nullptr, nullptr);

    // state = dialog_sym_rep @ graph_rep    [8192 x 256], K=4096  (BM=64 -> 256 blocks)
    gemm_tf32<0, 64, 0><<<dim3(DEMB / 128, B_SZ / 64), TB>>>(
        dialog_sym_rep, graph_p, state_p, nullptr, B_SZ, DEMB, E_SZ,
        nullptr, nullptr, nullptr, nullptr);

    // disease logits = f32(sym_mask) @ Wd1 + bd1   [8192 x 128], K=512 (int A fused)
    gemm_tf32<0, 64, 2><<<dim3(DIS / 128, B_SZ / 64), TB>>>(
        sym_mask, Wd1, dlog_p, bd1, B_SZ, DIS, SYM,
        nullptr, nullptr, nullptr, nullptr);

    // disease_dis = softmax(logits) * disease_mask -> out_dis
    softmax_mask_kernel<<<(B_SZ * 32 + TB - 1) / TB, TB>>>(dlog_p, disease_mask, out_dis);

    // h_mu = relu(ternary(dialog_state) @ Wm1 + bm1)  [8192 x 1024], K=640 (fused conv)
    gemm_tf32<1, 128, 1><<<dim3(HID / 128, B_SZ / 128), TB>>>(
        dialog_state, Wm1, hmu_p, bm1, B_SZ, HID, DSYM,
        nullptr, nullptr, nullptr, nullptr);

    // mu = sigmoid(h_mu @ Wm2 + bm2)        [8192 x 1]
    mu_kernel<<<(B_SZ * 32 + TB - 1) / TB, TB>>>(hmu_p, Wm2, bm2, mu_p);

    // h1 = relu(state @ W1 + b1)            [8192 x 1024], K=256
    gemm_tf32<1, 128, 0><<<dim3(HID / 128, B_SZ / 128), TB>>>(
        state_p, W1, h1_p, b1, B_SZ, HID, DEMB,
        nullptr, nullptr, nullptr, nullptr);

    // symptom_p = sigmoid(h1 @ W2 + b2)     [8192 x 512], K=1024
    gemm_tf32<2, 128, 0><<<dim3(SYM / 128, B_SZ / 128), TB>>>(
        h1_p, W2, symp_p, b2, B_SZ, SYM, HID,
        nullptr, nullptr, nullptr, nullptr);

    // final: sym_tfidf = disease_dis @ m_d; combine epilogue -> out_sym
    gemm_tf32<3, 128, 0><<<dim3(SYM / 128, B_SZ / 128), TB>>>(
        out_dis, m_d, out_sym, nullptr, B_SZ, SYM, DIS,
        mu_p, symp_p, sym_flag, symptoms_mask);
}